// round 1
// baseline (speedup 1.0000x reference)
#include <cuda_runtime.h>
#include <cuda_bf16.h>
#include <math.h>

#define NN   50000
#define EE   1600000
#define EP   (EE + NN)
#define GG   64
#define DIN  128
#define HID  64
#define HH1  4
#define F1   (HH1 * HID)   // 256
#define F2   HID           // 64
#define NEG_SLOPE 0.2f
#define BN_EPS 1e-5f

// ---------------- device scratch (no dynamic allocation allowed) ----------------
__device__ float g_xw1[(size_t)NN * F1];     // 51.2 MB
__device__ float g_h1 [(size_t)NN * F1];     // 51.2 MB
__device__ float g_xw2[(size_t)NN * F2];     // 12.8 MB
__device__ float g_h2 [(size_t)NN * F2];     // 12.8 MB
__device__ float g_as1[NN * HH1], g_ad1[NN * HH1];
__device__ float g_m1 [NN * HH1], g_sc1[NN * HH1];
__device__ float g_as2[NN], g_ad2[NN];
__device__ float g_m2 [NN], g_sc2[NN];
__device__ int   g_deg[NN];
__device__ int   g_rowptr[NN + 1];
__device__ int   g_cursor[NN];
__device__ int   g_colsrc[EP];
__device__ float g_gsum[GG * F2];
__device__ float g_gcnt[GG];

// ---------------- CSR build ----------------
__global__ void init_kernel() {
    int i = blockIdx.x * blockDim.x + threadIdx.x;
    if (i < NN) g_deg[i] = 1;                 // self loop
    if (i < GG * F2) g_gsum[i] = 0.f;
    if (i < GG) g_gcnt[i] = 0.f;
}

__global__ void count_kernel(const int* __restrict__ ei) {
    int i = blockIdx.x * blockDim.x + threadIdx.x;
    if (i < EE) atomicAdd(&g_deg[ei[EE + i]], 1);
}

// single-block scan over 50000 degrees
__global__ void scan_kernel() {
    __shared__ int sums[1024];
    const int T = 1024;
    int tid = threadIdx.x;
    int chunk = (NN + T - 1) / T;
    int begin = tid * chunk;
    int end = min(begin + chunk, NN);
    int s = 0;
    for (int i = begin; i < end; i++) s += g_deg[i];
    sums[tid] = s;
    __syncthreads();
    for (int off = 1; off < T; off <<= 1) {
        int v = 0;
        if (tid >= off) v = sums[tid - off];
        __syncthreads();
        sums[tid] += v;
        __syncthreads();
    }
    int run = sums[tid] - s;   // exclusive prefix of this chunk
    for (int i = begin; i < end; i++) {
        g_rowptr[i] = run;
        g_cursor[i] = run;
        run += g_deg[i];
    }
    if (tid == T - 1) g_rowptr[NN] = EP;
}

__global__ void fill_kernel(const int* __restrict__ ei) {
    int i = blockIdx.x * blockDim.x + threadIdx.x;
    if (i >= EP) return;
    int s, d;
    if (i < EE) { s = ei[i]; d = ei[EE + i]; }
    else        { s = d = i - EE; }
    int pos = atomicAdd(&g_cursor[d], 1);
    g_colsrc[pos] = s;
}

// ---------------- SGEMM: C[M,Nn] = A[M,K] @ B[K,Nn], Nn % 64 == 0, K % 16 == 0 ----------------
__global__ void sgemm_kernel(const float* __restrict__ A, const float* __restrict__ B,
                             float* __restrict__ C, int M, int Nn, int K) {
    __shared__ float As[16][65];
    __shared__ float Bs[16][64];
    int tid = threadIdx.x;          // 256 threads
    int tx = tid % 16, ty = tid / 16;
    int rb = blockIdx.y * 64, cb = blockIdx.x * 64;
    int aK = tid % 16, aR = tid / 16;
    int bN = tid % 64, bK = tid / 64;
    float acc[4][4] = {};
    for (int k0 = 0; k0 < K; k0 += 16) {
        #pragma unroll
        for (int p = 0; p < 4; p++) {
            int r = aR + p * 16;
            int gr = rb + r;
            As[aK][r] = (gr < M) ? A[(size_t)gr * K + k0 + aK] : 0.f;
        }
        #pragma unroll
        for (int p = 0; p < 4; p++) {
            int kk = bK + p * 4;
            Bs[kk][bN] = B[(size_t)(k0 + kk) * Nn + cb + bN];
        }
        __syncthreads();
        #pragma unroll
        for (int k = 0; k < 16; k++) {
            float ra[4], rbv[4];
            #pragma unroll
            for (int i = 0; i < 4; i++) ra[i] = As[k][ty + i * 16];
            #pragma unroll
            for (int j = 0; j < 4; j++) rbv[j] = Bs[k][tx + j * 16];
            #pragma unroll
            for (int i = 0; i < 4; i++)
                #pragma unroll
                for (int j = 0; j < 4; j++)
                    acc[i][j] += ra[i] * rbv[j];
        }
        __syncthreads();
    }
    #pragma unroll
    for (int i = 0; i < 4; i++) {
        int r = rb + ty + i * 16;
        if (r >= M) continue;
        #pragma unroll
        for (int j = 0; j < 4; j++) {
            int c = cb + tx + j * 16;
            C[(size_t)r * Nn + c] = acc[i][j];
        }
    }
}

// ---------------- per-node attention coefficients ----------------
template<int HHEADS>
__global__ void alpha_kernel(const float* __restrict__ xw, const float* __restrict__ asrc,
                             const float* __restrict__ adst,
                             float* __restrict__ as_, float* __restrict__ ad_) {
    int w = (blockIdx.x * blockDim.x + threadIdx.x) >> 5;
    int lane = threadIdx.x & 31;
    if (w >= NN * HHEADS) return;
    int n = w / HHEADS, h = w % HHEADS;
    const float* row = xw + (size_t)n * (HHEADS * 64) + h * 64;
    float x0 = row[lane], x1 = row[lane + 32];
    float s  = x0 * asrc[h * 64 + lane] + x1 * asrc[h * 64 + lane + 32];
    float dv = x0 * adst[h * 64 + lane] + x1 * adst[h * 64 + lane + 32];
    #pragma unroll
    for (int o = 16; o; o >>= 1) {
        s  += __shfl_xor_sync(~0u, s, o);
        dv += __shfl_xor_sync(~0u, dv, o);
    }
    if (!lane) { as_[n * HHEADS + h] = s; ad_[n * HHEADS + h] = dv; }
}

// ---------------- edge softmax stats: warp per dst node ----------------
template<int HHEADS>
__global__ void stats_kernel(const float* __restrict__ as_, const float* __restrict__ ad_,
                             float* __restrict__ m_, float* __restrict__ sc_) {
    int w = (blockIdx.x * blockDim.x + threadIdx.x) >> 5;
    if (w >= NN) return;
    int lane = threadIdx.x & 31;
    int s0 = g_rowptr[w], s1 = g_rowptr[w + 1];
    float ad[HHEADS], mx[HHEADS], sum[HHEADS];
    #pragma unroll
    for (int h = 0; h < HHEADS; h++) { ad[h] = ad_[w * HHEADS + h]; mx[h] = -1e30f; sum[h] = 0.f; }
    for (int j = s0 + lane; j < s1; j += 32) {
        int s = g_colsrc[j];
        #pragma unroll
        for (int h = 0; h < HHEADS; h++) {
            float e = as_[s * HHEADS + h] + ad[h];
            e = e >= 0.f ? e : NEG_SLOPE * e;
            mx[h] = fmaxf(mx[h], e);
        }
    }
    #pragma unroll
    for (int h = 0; h < HHEADS; h++)
        #pragma unroll
        for (int o = 16; o; o >>= 1) mx[h] = fmaxf(mx[h], __shfl_xor_sync(~0u, mx[h], o));
    for (int j = s0 + lane; j < s1; j += 32) {
        int s = g_colsrc[j];
        #pragma unroll
        for (int h = 0; h < HHEADS; h++) {
            float e = as_[s * HHEADS + h] + ad[h];
            e = e >= 0.f ? e : NEG_SLOPE * e;
            sum[h] += __expf(e - mx[h]);
        }
    }
    #pragma unroll
    for (int h = 0; h < HHEADS; h++)
        #pragma unroll
        for (int o = 16; o; o >>= 1) sum[h] += __shfl_xor_sync(~0u, sum[h], o);
    if (!lane) {
        #pragma unroll
        for (int h = 0; h < HHEADS; h++) {
            m_ [w * HHEADS + h] = mx[h];
            sc_[w * HHEADS + h] = 1.0f / (sum[h] + 1e-16f);
        }
    }
}

// ---------------- aggregation: one block per dst, SMEM-staged weights ----------------
// blockDim = HHEADS*64; fuses +bias, batchnorm(eval), relu
template<int HHEADS>
__global__ void agg_kernel(const float* __restrict__ xw,
                           const float* __restrict__ as_, const float* __restrict__ ad_,
                           const float* __restrict__ m_, const float* __restrict__ sc_,
                           const float* __restrict__ bias,
                           const float* __restrict__ bng, const float* __restrict__ bnb,
                           const float* __restrict__ bnm, const float* __restrict__ bnv,
                           float* __restrict__ hout) {
    constexpr int F = HHEADS * 64;
    const int d = blockIdx.x;
    const int tid = threadIdx.x;
    __shared__ float wsm[64 * HHEADS];
    __shared__ int   ssm[64];
    int s0 = g_rowptr[d], s1 = g_rowptr[d + 1];
    float acc = 0.f;
    for (int base = s0; base < s1; base += 64) {
        int cnt = min(64, s1 - base);
        if (tid < cnt * HHEADS) {
            int e = tid / HHEADS, h = tid % HHEADS;
            int s = g_colsrc[base + e];
            float ev = as_[s * HHEADS + h] + ad_[d * HHEADS + h];
            ev = ev >= 0.f ? ev : NEG_SLOPE * ev;
            wsm[e * HHEADS + h] = __expf(ev - m_[d * HHEADS + h]) * sc_[d * HHEADS + h];
            if (h == 0) ssm[e] = s;
        }
        __syncthreads();
        int h = tid >> 6;
        #pragma unroll 4
        for (int e = 0; e < cnt; e++)
            acc += wsm[e * HHEADS + h] * xw[(size_t)ssm[e] * F + tid];
        __syncthreads();
    }
    float o = acc + bias[tid];
    o = (o - bnm[tid]) * (bng[tid] * rsqrtf(bnv[tid] + BN_EPS)) + bnb[tid];
    hout[(size_t)d * F + tid] = fmaxf(o, 0.f);
}

// ---------------- global mean pool (warp per node) ----------------
__global__ void pool_kernel(const int* __restrict__ batch) {
    int w = (blockIdx.x * blockDim.x + threadIdx.x) >> 5;
    int lane = threadIdx.x & 31;
    if (w >= NN) return;
    int g = batch[w];
    atomicAdd(&g_gsum[g * F2 + lane],      g_h2[(size_t)w * F2 + lane]);
    atomicAdd(&g_gsum[g * F2 + lane + 32], g_h2[(size_t)w * F2 + lane + 32]);
    if (!lane) atomicAdd(&g_gcnt[g], 1.0f);
}

// ---------------- classifier head + log_softmax (block per graph) ----------------
__global__ void head_kernel(const float* __restrict__ Wc1, const float* __restrict__ bc1,
                            const float* __restrict__ Wc2, const float* __restrict__ bc2,
                            float* __restrict__ out) {
    __shared__ float repr[64];
    __shared__ float hc[64];
    __shared__ float logit[2];
    int g = blockIdx.x, j = threadIdx.x;
    float inv = 1.f / fmaxf(g_gcnt[g], 1.f);
    repr[j] = g_gsum[g * 64 + j] * inv;
    __syncthreads();
    float a = bc1[j];
    #pragma unroll
    for (int k = 0; k < 64; k++) a += repr[k] * Wc1[k * 64 + j];
    hc[j] = fmaxf(a, 0.f);
    __syncthreads();
    if (j < 2) {
        float l = bc2[j];
        for (int k = 0; k < 64; k++) l += hc[k] * Wc2[k * 2 + j];
        logit[j] = l;
    }
    __syncthreads();
    if (j == 0) {
        float l0 = logit[0], l1 = logit[1];
        float mx = fmaxf(l0, l1);
        float lse = mx + logf(expf(l0 - mx) + expf(l1 - mx));
        out[g * 2 + 0] = l0 - lse;
        out[g * 2 + 1] = l1 - lse;
    }
}

// ---------------- launch ----------------
extern "C" void kernel_launch(void* const* d_in, const int* in_sizes, int n_in,
                              void* d_out, int out_size) {
    const float* x        = (const float*)d_in[0];
    const int*   ei       = (const int*)  d_in[1];
    const int*   batch    = (const int*)  d_in[2];
    const float* W1       = (const float*)d_in[3];
    const float* att_src1 = (const float*)d_in[4];
    const float* att_dst1 = (const float*)d_in[5];
    const float* bias1    = (const float*)d_in[6];
    const float* bn1_g    = (const float*)d_in[7];
    const float* bn1_b    = (const float*)d_in[8];
    const float* bn1_m    = (const float*)d_in[9];
    const float* bn1_v    = (const float*)d_in[10];
    const float* W2       = (const float*)d_in[11];
    const float* att_src2 = (const float*)d_in[12];
    const float* att_dst2 = (const float*)d_in[13];
    const float* bias2    = (const float*)d_in[14];
    const float* bn2_g    = (const float*)d_in[15];
    const float* bn2_b    = (const float*)d_in[16];
    const float* bn2_m    = (const float*)d_in[17];
    const float* bn2_v    = (const float*)d_in[18];
    const float* Wc1      = (const float*)d_in[19];
    const float* bc1      = (const float*)d_in[20];
    const float* Wc2      = (const float*)d_in[21];
    const float* bc2      = (const float*)d_in[22];
    float* out = (float*)d_out;

    // pointers to device globals (usable directly inside kernels)
    float *p_xw1, *p_h1, *p_xw2, *p_h2;
    cudaGetSymbolAddress((void**)&p_xw1, g_xw1);
    cudaGetSymbolAddress((void**)&p_h1,  g_h1);
    cudaGetSymbolAddress((void**)&p_xw2, g_xw2);
    cudaGetSymbolAddress((void**)&p_h2,  g_h2);
    float *p_as1, *p_ad1, *p_m1, *p_sc1, *p_as2, *p_ad2, *p_m2, *p_sc2;
    cudaGetSymbolAddress((void**)&p_as1, g_as1);
    cudaGetSymbolAddress((void**)&p_ad1, g_ad1);
    cudaGetSymbolAddress((void**)&p_m1,  g_m1);
    cudaGetSymbolAddress((void**)&p_sc1, g_sc1);
    cudaGetSymbolAddress((void**)&p_as2, g_as2);
    cudaGetSymbolAddress((void**)&p_ad2, g_ad2);
    cudaGetSymbolAddress((void**)&p_m2,  g_m2);
    cudaGetSymbolAddress((void**)&p_sc2, g_sc2);

    // CSR build
    init_kernel<<<(NN + 255) / 256, 256>>>();
    count_kernel<<<(EE + 255) / 256, 256>>>(ei);
    scan_kernel<<<1, 1024>>>();
    fill_kernel<<<(EP + 255) / 256, 256>>>(ei);

    // ---- layer 1 ----
    sgemm_kernel<<<dim3(F1 / 64, (NN + 63) / 64), 256>>>(x, W1, p_xw1, NN, F1, DIN);
    alpha_kernel<HH1><<<(NN * HH1 * 32 + 255) / 256, 256>>>(p_xw1, att_src1, att_dst1, p_as1, p_ad1);
    stats_kernel<HH1><<<(NN * 32 + 255) / 256, 256>>>(p_as1, p_ad1, p_m1, p_sc1);
    agg_kernel<HH1><<<NN, 256>>>(p_xw1, p_as1, p_ad1, p_m1, p_sc1,
                                 bias1, bn1_g, bn1_b, bn1_m, bn1_v, p_h1);

    // ---- layer 2 ----
    sgemm_kernel<<<dim3(F2 / 64, (NN + 63) / 64), 256>>>(p_h1, W2, p_xw2, NN, F2, F1);
    alpha_kernel<1><<<(NN * 32 + 255) / 256, 256>>>(p_xw2, att_src2, att_dst2, p_as2, p_ad2);
    stats_kernel<1><<<(NN * 32 + 255) / 256, 256>>>(p_as2, p_ad2, p_m2, p_sc2);
    agg_kernel<1><<<NN, 64>>>(p_xw2, p_as2, p_ad2, p_m2, p_sc2,
                              bias2, bn2_g, bn2_b, bn2_m, bn2_v, p_h2);

    // ---- pooling + classifier ----
    pool_kernel<<<(NN * 32 + 255) / 256, 256>>>(batch);
    head_kernel<<<GG, 64>>>(Wc1, bc1, Wc2, bc2, out);
}

// round 3
// speedup vs baseline: 1.1371x; 1.1371x over previous
#include <cuda_runtime.h>
#include <cuda_fp16.h>
#include <math.h>

#define NN   50000
#define EE   1600000
#define EP   (EE + NN)
#define GG   64
#define DIN  128
#define HID  64
#define HH1  4
#define F1   (HH1 * HID)   // 256
#define F2   HID           // 64
#define NEG_SLOPE 0.2f
#define BN_EPS 1e-5f

// ---------------- device scratch ----------------
__device__ __half g_xw1h[(size_t)NN * F1];   // 25.6 MB (fp16 gather table)
__device__ __half g_xw2h[(size_t)NN * F2];   // 6.4 MB
__device__ float  g_h1 [(size_t)NN * F1];    // 51.2 MB (layer-2 GEMM input)
__device__ float  g_as1[NN * HH1], g_ad1[NN * HH1];
__device__ float  g_m1 [NN * HH1], g_sc1[NN * HH1];
__device__ float  g_as2[NN], g_ad2[NN];
__device__ float  g_m2 [NN], g_sc2[NN];
__device__ int    g_deg[NN];
__device__ int    g_rowptr[NN + 1];
__device__ int    g_cursor[NN];
__device__ int    g_colsrc[EP];
__device__ float  g_gsum[GG * F2];
__device__ float  g_gcnt[GG];

// ---------------- CSR build + init ----------------
__global__ void init_kernel() {
    int i = blockIdx.x * blockDim.x + threadIdx.x;
    if (i < NN) g_deg[i] = 1;                 // self loop
    if (i < GG * F2) g_gsum[i] = 0.f;
    if (i < GG) g_gcnt[i] = 0.f;
}

__global__ void count_kernel(const int* __restrict__ ei, const int* __restrict__ batch) {
    int i = blockIdx.x * blockDim.x + threadIdx.x;
    if (i < EE) atomicAdd(&g_deg[ei[EE + i]], 1);
    if (i < NN) atomicAdd(&g_gcnt[batch[i]], 1.0f);
}

__global__ void scan_kernel() {
    __shared__ int sums[1024];
    const int T = 1024;
    int tid = threadIdx.x;
    int chunk = (NN + T - 1) / T;
    int begin = tid * chunk;
    int end = min(begin + chunk, NN);
    int s = 0;
    for (int i = begin; i < end; i++) s += g_deg[i];
    sums[tid] = s;
    __syncthreads();
    for (int off = 1; off < T; off <<= 1) {
        int v = 0;
        if (tid >= off) v = sums[tid - off];
        __syncthreads();
        sums[tid] += v;
        __syncthreads();
    }
    int run = sums[tid] - s;
    for (int i = begin; i < end; i++) {
        g_rowptr[i] = run;
        g_cursor[i] = run;
        run += g_deg[i];
    }
    if (tid == T - 1) g_rowptr[NN] = EP;
}

__global__ void fill_kernel(const int* __restrict__ ei) {
    int i = blockIdx.x * blockDim.x + threadIdx.x;
    if (i >= EP) return;
    int s, d;
    if (i < EE) { s = ei[i]; d = ei[EE + i]; }
    else        { s = d = i - EE; }
    int pos = atomicAdd(&g_cursor[d], 1);
    g_colsrc[pos] = s;
}

// ---------------- SGEMM 128x64 tile, 8x4/thread, fused fp16-store + alpha epilogue ----
// C (logical fp32) = A[M,K] @ B[K,Nn]; writes Ch (half) and per-(row,head) alpha dots.
// BN = 64 == head width, so blockIdx.x == head index. HEADS = Nn/64.
template<int HEADS>
__global__ void sgemm_fused_kernel(const float* __restrict__ A, const float* __restrict__ B,
                                   __half* __restrict__ Ch,
                                   const float* __restrict__ att_src,
                                   const float* __restrict__ att_dst,
                                   float* __restrict__ as_, float* __restrict__ ad_,
                                   int M, int Nn, int K) {
    __shared__ float As[16][132];   // [k][m], padded
    __shared__ float Bs[16][64];
    const int t  = threadIdx.x;     // 256 threads
    const int tx = t & 15;          // 0..15 col group (4 cols each)
    const int ty = t >> 4;          // 0..15 row group (8 rows each)
    const int rb = blockIdx.y * 128;
    const int cb = blockIdx.x * 64;
    const int head = blockIdx.x;

    float acc[8][4] = {};

    for (int k0 = 0; k0 < K; k0 += 16) {
        #pragma unroll
        for (int r = 0; r < 2; r++) {
            int idx = t + r * 256;          // 0..511
            int row = idx >> 2;             // 0..127
            int kq  = (idx & 3) * 4;
            float4 v = make_float4(0.f, 0.f, 0.f, 0.f);
            int gr = rb + row;
            if (gr < M) v = *(const float4*)&A[(size_t)gr * K + k0 + kq];
            As[kq + 0][row] = v.x; As[kq + 1][row] = v.y;
            As[kq + 2][row] = v.z; As[kq + 3][row] = v.w;
        }
        {
            int brow = t >> 4, bcol = (t & 15) * 4;
            *(float4*)&Bs[brow][bcol] =
                *(const float4*)&B[(size_t)(k0 + brow) * Nn + cb + bcol];
        }
        __syncthreads();
        #pragma unroll
        for (int kk = 0; kk < 16; kk++) {
            float a[8];
            *(float4*)&a[0] = *(float4*)&As[kk][ty * 8];
            *(float4*)&a[4] = *(float4*)&As[kk][ty * 8 + 4];
            float4 b = *(float4*)&Bs[kk][tx * 4];
            #pragma unroll
            for (int i = 0; i < 8; i++) {
                acc[i][0] += a[i] * b.x;
                acc[i][1] += a[i] * b.y;
                acc[i][2] += a[i] * b.z;
                acc[i][3] += a[i] * b.w;
            }
        }
        __syncthreads();
    }

    // attention vectors segment for this thread's 4 columns
    float4 asv = *(const float4*)&att_src[head * 64 + tx * 4];
    float4 adv = *(const float4*)&att_dst[head * 64 + tx * 4];

    #pragma unroll
    for (int i = 0; i < 8; i++) {
        int row = rb + ty * 8 + i;
        bool ok = row < M;
        if (ok) {
            __half2* outp = (__half2*)&Ch[(size_t)row * Nn + cb + tx * 4];
            outp[0] = __floats2half2_rn(acc[i][0], acc[i][1]);
            outp[1] = __floats2half2_rn(acc[i][2], acc[i][3]);
        }
        float sp = acc[i][0] * asv.x + acc[i][1] * asv.y + acc[i][2] * asv.z + acc[i][3] * asv.w;
        float dp = acc[i][0] * adv.x + acc[i][1] * adv.y + acc[i][2] * adv.z + acc[i][3] * adv.w;
        #pragma unroll
        for (int off = 8; off; off >>= 1) {
            sp += __shfl_xor_sync(0xffffffffu, sp, off);
            dp += __shfl_xor_sync(0xffffffffu, dp, off);
        }
        if (tx == 0 && ok) {
            as_[row * HEADS + head] = sp;
            ad_[row * HEADS + head] = dp;
        }
    }
}

// ---------------- one-pass online softmax stats: warp per dst node --------------
template<int HHEADS>
__global__ void stats_kernel(const float* __restrict__ as_, const float* __restrict__ ad_,
                             float* __restrict__ m_, float* __restrict__ sc_) {
    int w = (blockIdx.x * blockDim.x + threadIdx.x) >> 5;
    if (w >= NN) return;
    int lane = threadIdx.x & 31;
    int s0 = g_rowptr[w], s1 = g_rowptr[w + 1];
    float ad[HHEADS], mx[HHEADS], sum[HHEADS];
    #pragma unroll
    for (int h = 0; h < HHEADS; h++) {
        ad[h] = ad_[w * HHEADS + h]; mx[h] = -1e30f; sum[h] = 0.f;
    }
    for (int j = s0 + lane; j < s1; j += 32) {
        int s = g_colsrc[j];
        float av[HHEADS];
        if (HHEADS == 4) {
            float4 v = *(const float4*)&as_[(size_t)s * 4];
            av[0] = v.x; av[1 % HHEADS] = v.y; av[2 % HHEADS] = v.z; av[3 % HHEADS] = v.w;
        } else {
            #pragma unroll
            for (int h = 0; h < HHEADS; h++) av[h] = as_[s * HHEADS + h];
        }
        #pragma unroll
        for (int h = 0; h < HHEADS; h++) {
            float e = av[h] + ad[h];
            e = e >= 0.f ? e : NEG_SLOPE * e;
            float nm = fmaxf(mx[h], e);
            sum[h] = sum[h] * __expf(mx[h] - nm) + __expf(e - nm);
            mx[h] = nm;
        }
    }
    #pragma unroll
    for (int h = 0; h < HHEADS; h++) {
        #pragma unroll
        for (int off = 16; off; off >>= 1) {
            float mo = __shfl_xor_sync(0xffffffffu, mx[h], off);
            float so = __shfl_xor_sync(0xffffffffu, sum[h], off);
            float nm = fmaxf(mx[h], mo);
            sum[h] = sum[h] * __expf(mx[h] - nm) + so * __expf(mo - nm);
            mx[h] = nm;
        }
    }
    if (!lane) {
        #pragma unroll
        for (int h = 0; h < HHEADS; h++) {
            m_ [w * HHEADS + h] = mx[h];
            sc_[w * HHEADS + h] = 1.0f / (sum[h] + 1e-16f);
        }
    }
}

// ---------------- aggregation over fp16 gather table ---------------------------
// block per dst, blockDim = HHEADS*64; fuses +bias, BN(eval), relu.
// POOL: instead of writing hout, atomically accumulate into per-graph sums.
template<int HHEADS, bool POOL>
__global__ void agg_kernel(const __half* __restrict__ xwh,
                           const float* __restrict__ as_, const float* __restrict__ ad_,
                           const float* __restrict__ m_, const float* __restrict__ sc_,
                           const float* __restrict__ bias,
                           const float* __restrict__ bng, const float* __restrict__ bnb,
                           const float* __restrict__ bnm, const float* __restrict__ bnv,
                           float* __restrict__ hout, const int* __restrict__ batch) {
    constexpr int F = HHEADS * 64;
    const int d = blockIdx.x;
    const int tid = threadIdx.x;
    __shared__ float wsm[64 * HHEADS];
    __shared__ int   ssm[64];
    int s0 = g_rowptr[d], s1 = g_rowptr[d + 1];
    float acc = 0.f;
    for (int base = s0; base < s1; base += 64) {
        int cnt = min(64, s1 - base);
        if (tid < cnt * HHEADS) {
            int e = tid / HHEADS, h = tid % HHEADS;
            int s = g_colsrc[base + e];
            float ev = as_[s * HHEADS + h] + ad_[d * HHEADS + h];
            ev = ev >= 0.f ? ev : NEG_SLOPE * ev;
            wsm[e * HHEADS + h] = __expf(ev - m_[d * HHEADS + h]) * sc_[d * HHEADS + h];
            if (h == 0) ssm[e] = s;
        }
        __syncthreads();
        int h = tid >> 6;
        #pragma unroll 4
        for (int e = 0; e < cnt; e++)
            acc += wsm[e * HHEADS + h] * __half2float(xwh[(size_t)ssm[e] * F + tid]);
        __syncthreads();
    }
    float o = acc + bias[tid];
    o = (o - bnm[tid]) * (bng[tid] * rsqrtf(bnv[tid] + BN_EPS)) + bnb[tid];
    o = fmaxf(o, 0.f);
    if (POOL) {
        atomicAdd(&g_gsum[batch[d] * F2 + tid], o);
    } else {
        hout[(size_t)d * F + tid] = o;
    }
}

// ---------------- classifier head + log_softmax (block per graph) ----------------
__global__ void head_kernel(const float* __restrict__ Wc1, const float* __restrict__ bc1,
                            const float* __restrict__ Wc2, const float* __restrict__ bc2,
                            float* __restrict__ out) {
    __shared__ float repr[64];
    __shared__ float hc[64];
    __shared__ float logit[2];
    int g = blockIdx.x, j = threadIdx.x;
    float inv = 1.f / fmaxf(g_gcnt[g], 1.f);
    repr[j] = g_gsum[g * 64 + j] * inv;
    __syncthreads();
    float a = bc1[j];
    #pragma unroll
    for (int k = 0; k < 64; k++) a += repr[k] * Wc1[k * 64 + j];
    hc[j] = fmaxf(a, 0.f);
    __syncthreads();
    if (j < 2) {
        float l = bc2[j];
        for (int k = 0; k < 64; k++) l += hc[k] * Wc2[k * 2 + j];
        logit[j] = l;
    }
    __syncthreads();
    if (j == 0) {
        float l0 = logit[0], l1 = logit[1];
        float mx = fmaxf(l0, l1);
        float lse = mx + logf(expf(l0 - mx) + expf(l1 - mx));
        out[g * 2 + 0] = l0 - lse;
        out[g * 2 + 1] = l1 - lse;
    }
}

// ---------------- launch ----------------
extern "C" void kernel_launch(void* const* d_in, const int* in_sizes, int n_in,
                              void* d_out, int out_size) {
    const float* x        = (const float*)d_in[0];
    const int*   ei       = (const int*)  d_in[1];
    const int*   batch    = (const int*)  d_in[2];
    const float* W1       = (const float*)d_in[3];
    const float* att_src1 = (const float*)d_in[4];
    const float* att_dst1 = (const float*)d_in[5];
    const float* bias1    = (const float*)d_in[6];
    const float* bn1_g    = (const float*)d_in[7];
    const float* bn1_b    = (const float*)d_in[8];
    const float* bn1_m    = (const float*)d_in[9];
    const float* bn1_v    = (const float*)d_in[10];
    const float* W2       = (const float*)d_in[11];
    const float* att_src2 = (const float*)d_in[12];
    const float* att_dst2 = (const float*)d_in[13];
    const float* bias2    = (const float*)d_in[14];
    const float* bn2_g    = (const float*)d_in[15];
    const float* bn2_b    = (const float*)d_in[16];
    const float* bn2_m    = (const float*)d_in[17];
    const float* bn2_v    = (const float*)d_in[18];
    const float* Wc1      = (const float*)d_in[19];
    const float* bc1      = (const float*)d_in[20];
    const float* Wc2      = (const float*)d_in[21];
    const float* bc2      = (const float*)d_in[22];
    float* out = (float*)d_out;

    __half *p_xw1h, *p_xw2h;
    float *p_h1;
    cudaGetSymbolAddress((void**)&p_xw1h, g_xw1h);
    cudaGetSymbolAddress((void**)&p_xw2h, g_xw2h);
    cudaGetSymbolAddress((void**)&p_h1,  g_h1);
    float *p_as1, *p_ad1, *p_m1, *p_sc1, *p_as2, *p_ad2, *p_m2, *p_sc2;
    cudaGetSymbolAddress((void**)&p_as1, g_as1);
    cudaGetSymbolAddress((void**)&p_ad1, g_ad1);
    cudaGetSymbolAddress((void**)&p_m1,  g_m1);
    cudaGetSymbolAddress((void**)&p_sc1, g_sc1);
    cudaGetSymbolAddress((void**)&p_as2, g_as2);
    cudaGetSymbolAddress((void**)&p_ad2, g_ad2);
    cudaGetSymbolAddress((void**)&p_m2,  g_m2);
    cudaGetSymbolAddress((void**)&p_sc2, g_sc2);

    // CSR build + init
    init_kernel<<<(NN + 255) / 256, 256>>>();
    count_kernel<<<(EE + 255) / 256, 256>>>(ei, batch);
    scan_kernel<<<1, 1024>>>();
    fill_kernel<<<(EP + 255) / 256, 256>>>(ei);

    const int MB = (NN + 127) / 128;   // 391

    // ---- layer 1 ----
    sgemm_fused_kernel<HH1><<<dim3(F1 / 64, MB), 256>>>(
        x, W1, p_xw1h, att_src1, att_dst1, p_as1, p_ad1, NN, F1, DIN);
    stats_kernel<HH1><<<(NN * 32 + 255) / 256, 256>>>(p_as1, p_ad1, p_m1, p_sc1);
    agg_kernel<HH1, false><<<NN, 256>>>(p_xw1h, p_as1, p_ad1, p_m1, p_sc1,
                                        bias1, bn1_g, bn1_b, bn1_m, bn1_v, p_h1, nullptr);

    // ---- layer 2 ----
    sgemm_fused_kernel<1><<<dim3(F2 / 64, MB), 256>>>(
        p_h1, W2, p_xw2h, att_src2, att_dst2, p_as2, p_ad2, NN, F2, F1);
    stats_kernel<1><<<(NN * 32 + 255) / 256, 256>>>(p_as2, p_ad2, p_m2, p_sc2);
    agg_kernel<1, true><<<NN, 64>>>(p_xw2h, p_as2, p_ad2, p_m2, p_sc2,
                                    bias2, bn2_g, bn2_b, bn2_m, bn2_v, nullptr, batch);

    // ---- classifier ----
    head_kernel<<<GG, 64>>>(Wc1, bc1, Wc2, bc2, out);
}